// round 16
// baseline (speedup 1.0000x reference)
#include <cuda_runtime.h>
#include <cuda_fp16.h>
#include <math.h>
#include <stdint.h>

#define BB 4
#define NN 8192
#define DIMV 256
#define HH 8
#define HD 32
#define INTERNAL 256
#define MROWS (BB * NN)        // 32768
#define QKVO_COLS 1024
#define SCALE_F 0.17677669529663687f

// ---------------- persistent device scratch (no allocations) ----------------
__device__ __half g_qkvo[(size_t)MROWS * QKVO_COLS];    // 67 MB fp16
__device__ __half g_xh [(size_t)MROWS * DIMV];
__device__ __half g_ph [(size_t)MROWS * INTERNAL];
__device__ __half g_wqh[(size_t)QKVO_COLS * DIMV];
__device__ __half g_pwh[(size_t)DIMV * INTERNAL];
__device__ float g_kv  [BB * HH * HD * HD];
__device__ float g_ksum[BB * HH * HD];
__device__ float g_vsum[BB * HH * HD];

__device__ __forceinline__ uint32_t smem_u32(const void* p) {
    uint32_t a;
    asm("{ .reg .u64 t; cvta.to.shared.u64 t, %1; cvt.u32.u64 %0, t; }"
        : "=r"(a) : "l"(p));
    return a;
}

__device__ __forceinline__ void ldmx4(uint32_t* r, uint32_t addr) {
    asm volatile("ldmatrix.sync.aligned.m8n8.x4.shared.b16 {%0,%1,%2,%3}, [%4];"
        : "=r"(r[0]), "=r"(r[1]), "=r"(r[2]), "=r"(r[3]) : "r"(addr));
}
__device__ __forceinline__ void ldmx2(uint32_t* r, uint32_t addr) {
    asm volatile("ldmatrix.sync.aligned.m8n8.x2.shared.b16 {%0,%1}, [%2];"
        : "=r"(r[0]), "=r"(r[1]) : "r"(addr));
}

__device__ __forceinline__ void mma16816h(float* d, const uint32_t* a,
                                          uint32_t b0, uint32_t b1) {
    asm volatile(
        "mma.sync.aligned.m16n8k16.row.col.f32.f16.f16.f32 "
        "{%0,%1,%2,%3}, {%4,%5,%6,%7}, {%8,%9}, {%0,%1,%2,%3};"
        : "+f"(d[0]), "+f"(d[1]), "+f"(d[2]), "+f"(d[3])
        : "r"(a[0]), "r"(a[1]), "r"(a[2]), "r"(a[3]), "r"(b0), "r"(b1));
}

__device__ __forceinline__ void cp16(uint32_t saddr, const void* gaddr) {
    asm volatile("cp.async.cg.shared.global [%0], [%1], 16;"
        :: "r"(saddr), "l"(gaddr) : "memory");
}
#define CP_COMMIT() asm volatile("cp.async.commit_group;" ::: "memory")
#define CP_WAIT(n)  asm volatile("cp.async.wait_group %0;" :: "n"(n) : "memory")

// ---------------- fused fp32->fp16 conversion + accumulator zeroing ---------
#define CVT_N1 (MROWS * DIMV / 4)
#define CVT_N2 (QKVO_COLS * DIMV / 4)
#define CVT_N3 (DIMV * INTERNAL / 4)
__global__ void __launch_bounds__(256)
cvt_all_kernel(const float* __restrict__ x, const float* __restrict__ wq,
               const float* __restrict__ pw, __half* __restrict__ xh,
               __half* __restrict__ wqh, __half* __restrict__ pwh)
{
    int i = blockIdx.x * 256 + threadIdx.x;
    if (i < BB * HH * HD * HD) g_kv[i] = 0.f;
    if (i < BB * HH * HD) { g_ksum[i] = 0.f; g_vsum[i] = 0.f; }

    const float* s; __half* d; int j;
    if (i < CVT_N1) { s = x; d = xh; j = i; }
    else if (i < CVT_N1 + CVT_N2) { s = wq; d = wqh; j = i - CVT_N1; }
    else if (i < CVT_N1 + CVT_N2 + CVT_N3) { s = pw; d = pwh; j = i - CVT_N1 - CVT_N2; }
    else return;
    float4 v = ((const float4*)s)[j];
    __half2 h0 = __floats2half2_rn(v.x, v.y);
    __half2 h1 = __floats2half2_rn(v.z, v.w);
    uint2 o = { *reinterpret_cast<uint32_t*>(&h0), *reinterpret_cast<uint32_t*>(&h1) };
    ((uint2*)d)[j] = o;
}

// =================== HMMA GEMM (single fp16, 4-stage cp.async) ==============
#define ROWB 80
#define ST_A 0
#define ST_B 10240
#define STAGEB 20480
#define NSTAGE 4
#define GEMM_SMEM_BYTES (NSTAGE * STAGEB)   // 80 KB

template <typename OutT>
__global__ void __launch_bounds__(256)
gemm_h_kernel(const __half* __restrict__ A, const __half* __restrict__ Bw,
              const float* __restrict__ bias, OutT* __restrict__ C,
              int M, int Nn, int K)
{
    extern __shared__ char sm[];
    const uint32_t smb = smem_u32(sm);
    const int tid  = threadIdx.x;
    const int wid  = tid >> 5;
    const int lane = tid & 31;
    const int m0 = blockIdx.y * 128;
    const int n0 = blockIdx.x * 128;
    const int wm0 = (wid & 3) * 32;
    const int wn0 = (wid >> 2) * 64;

    const int a_row = (lane & 7) + ((lane >> 3) & 1) * 8;
    const int a_kh  = (lane >> 4) * 8;
    const int b_row = (lane & 7) + ((lane >> 4) & 1) * 8;
    const int b_kh  = ((lane >> 3) & 1) * 8;

    float acc[2][8][4];
#pragma unroll
    for (int i = 0; i < 2; i++)
#pragma unroll
        for (int j = 0; j < 8; j++)
#pragma unroll
            for (int l = 0; l < 4; l++) acc[i][j][l] = 0.f;

    const int NCH = K / 32;
    const int row2 = tid >> 2;
    const int seg  = tid & 3;

#define LOAD_STAGE(c, buf) do {                                              \
    int k0 = (c) * 32;                                                       \
    uint32_t base = smb + (buf) * STAGEB;                                    \
    _Pragma("unroll")                                                        \
    for (int i = 0; i < 2; i++) {                                            \
        int r = row2 + i * 64;                                               \
        uint32_t so = r * ROWB + seg * 16;                                   \
        cp16(base + ST_A + so, A  + (size_t)(m0 + r) * K + k0 + seg * 8);    \
        cp16(base + ST_B + so, Bw + (size_t)(n0 + r) * K + k0 + seg * 8);    \
    }                                                                        \
    CP_COMMIT();                                                             \
} while (0)

    LOAD_STAGE(0, 0);
    LOAD_STAGE(1, 1);
    LOAD_STAGE(2, 2);

    for (int c = 0; c < NCH; c++) {
        CP_WAIT(2);
        __syncthreads();
        const uint32_t base = smb + (c & (NSTAGE - 1)) * STAGEB;

#pragma unroll
        for (int ks = 0; ks < 2; ks++) {
            uint32_t af[2][4], bf[4][4];
#pragma unroll
            for (int mf = 0; mf < 2; mf++)
                ldmx4(af[mf], base + ST_A + (wm0 + mf * 16 + a_row) * ROWB
                                        + (ks * 16 + a_kh) * 2);
#pragma unroll
            for (int nf2 = 0; nf2 < 4; nf2++)
                ldmx4(bf[nf2], base + ST_B + (wn0 + nf2 * 16 + b_row) * ROWB
                                          + (ks * 16 + b_kh) * 2);
#pragma unroll
            for (int nf2 = 0; nf2 < 4; nf2++)
#pragma unroll
                for (int mf = 0; mf < 2; mf++)
#pragma unroll
                    for (int s = 0; s < 2; s++)
                        mma16816h(acc[mf][nf2 * 2 + s], af[mf],
                                  bf[nf2][s * 2], bf[nf2][s * 2 + 1]);
        }
        if (c + 3 < NCH) LOAD_STAGE(c + 3, (c + 3) & (NSTAGE - 1));
        else CP_COMMIT();
    }
#undef LOAD_STAGE

    const int rr = lane >> 2;
    const int cc = (lane & 3) * 2;
#pragma unroll
    for (int mf = 0; mf < 2; mf++) {
        int r0 = m0 + wm0 + mf * 16 + rr;
#pragma unroll
        for (int nf = 0; nf < 8; nf++) {
            int col = n0 + wn0 + nf * 8 + cc;
            float b0 = bias[col], b1 = bias[col + 1];
            float o00 = acc[mf][nf][0] + b0, o01 = acc[mf][nf][1] + b1;
            float o10 = acc[mf][nf][2] + b0, o11 = acc[mf][nf][3] + b1;
            if (sizeof(OutT) == 2) {
                __half2 p0 = __floats2half2_rn(o00, o01);
                __half2 p1 = __floats2half2_rn(o10, o11);
                *(__half2*)&C[(size_t)r0 * Nn + col] = p0;
                *(__half2*)&C[(size_t)(r0 + 8) * Nn + col] = p1;
            } else {
                float2 v0 = {o00, o01}, v1 = {o10, o11};
                *(float2*)&C[(size_t)r0 * Nn + col] = v0;
                *(float2*)&C[(size_t)(r0 + 8) * Nn + col] = v1;
            }
        }
    }
}

// ---------------- stats v5: tensor-core kv_state, smem reuse ----------------
#define STW 5120
#define KVROW 34
#define STATS_SMEM (8 * STW)       // 40960 B

__global__ void __launch_bounds__(256)
stats_kernel(const __half* __restrict__ qkvo,
             const float* __restrict__ sinp, const float* __restrict__ cosp)
{
    extern __shared__ char ssm[];
    const int tid  = threadIdx.x;
    const int w    = tid >> 5;
    const int lane = tid & 31;
    const int bh = blockIdx.x;
    const int b = bh >> 3, h = bh & 7;
    const int nb = blockIdx.y * 256 + w * 32;

    char* smw = ssm + w * STW;
    char* smv = smw + 2560;
    const uint32_t ks_u = smem_u32(smw);
    const uint32_t v_u  = smem_u32(smv);

    const __half* kbase = qkvo + (size_t)(b * NN + nb) * QKVO_COLS + 256 + h * 32 + lane;
    const __half* vbase = kbase + 256;

    float ksum_acc = 0.f, vsum_acc = 0.f;

#pragma unroll
    for (int g = 0; g < 4; g++) {
        float kr[8], vr[8], sv[8], cv[8];
#pragma unroll
        for (int i = 0; i < 8; i++) {
            kr[i] = __half2float(kbase[(size_t)(g * 8 + i) * QKVO_COLS]);
            vr[i] = __half2float(vbase[(size_t)(g * 8 + i) * QKVO_COLS]);
        }
#pragma unroll
        for (int i = 0; i < 8; i++) {
            sv[i] = sinp[(nb + g * 8 + i) * HD + lane];
            cv[i] = cosp[(nb + g * 8 + i) * HD + lane];
        }
        __half ksh[8], vh[8];
#pragma unroll
        for (int i = 0; i < 8; i++) {
            float kh = (kr[i] > 0.f) ? (kr[i] + 1.f) : __expf(kr[i]);
            ksum_acc += kh;
            vsum_acc += vr[i];
            float partner = __shfl_xor_sync(0xffffffffu, kh, 1);
            float rot = (lane & 1) ? partner : -partner;
            ksh[i] = __float2half(kh * cv[i] + rot * sv[i]);
            vh[i]  = __float2half(vr[i]);
        }
#pragma unroll
        for (int i = 0; i < 8; i += 2) {
            int n = g * 8 + i;
            __half2 pk = {ksh[i], ksh[i + 1]};
            __half2 pv = {vh[i],  vh[i + 1]};
            *(__half2*)(smw + lane * 80 + n * 2) = pk;
            *(__half2*)(smv + lane * 80 + n * 2) = pv;
        }
    }
    __syncwarp();

    float kv[2][4][4];
#pragma unroll
    for (int mt = 0; mt < 2; mt++)
#pragma unroll
        for (int et = 0; et < 4; et++)
#pragma unroll
            for (int l = 0; l < 4; l++) kv[mt][et][l] = 0.f;

#pragma unroll
    for (int ks = 0; ks < 2; ks++) {
        const int k0 = ks * 16;
        uint32_t af[2][4];
#pragma unroll
        for (int mt = 0; mt < 2; mt++)
            ldmx4(af[mt], ks_u + (mt * 16 + (lane & 7) + ((lane >> 3) & 1) * 8) * 80
                               + (k0 + (lane >> 4) * 8) * 2);
#pragma unroll
        for (int et = 0; et < 4; et++) {
            uint32_t bf[2];
            ldmx2(bf, v_u + (et * 8 + (lane & 7)) * 80
                          + (k0 + ((lane >> 3) & 1) * 8) * 2);
#pragma unroll
            for (int mt = 0; mt < 2; mt++)
                mma16816h(kv[mt][et], af[mt], bf[0], bf[1]);
        }
    }
    __syncwarp();

    float* kvw = (float*)(ssm + w * STW);
    const int dm = lane >> 2;
    const int de = (lane & 3) * 2;
#pragma unroll
    for (int mt = 0; mt < 2; mt++)
#pragma unroll
        for (int et = 0; et < 4; et++) {
            float2 lo = {kv[mt][et][0], kv[mt][et][1]};
            float2 hi = {kv[mt][et][2], kv[mt][et][3]};
            *(float2*)&kvw[(mt * 16 + dm) * KVROW + et * 8 + de] = lo;
            *(float2*)&kvw[(mt * 16 + dm + 8) * KVROW + et * 8 + de] = hi;
        }

    atomicAdd(&g_ksum[bh * HD + lane], ksum_acc);
    atomicAdd(&g_vsum[bh * HD + lane], vsum_acc);

    __syncthreads();

    const float* kvs = (const float*)ssm;
#pragma unroll
    for (int o = 0; o < 4; o++) {
        int idx = o * 256 + tid;
        int m = idx >> 5, e = idx & 31;
        float s = 0.f;
#pragma unroll
        for (int ww = 0; ww < 8; ww++)
            s += kvs[ww * (STW / 4) + m * KVROW + e];
        atomicAdd(&g_kv[bh * (HD * HD) + m * HD + e], s);
    }
}

// ---------------- fuse v6: channel-half split, 64 tokens x 4 heads ----------
// Block = 64 tokens x 128 channels (4 heads). Warps 0-3: heads, rows 0-31;
// warps 4-7: same heads, rows 32-63. Staging = 4 heads' kvT only (18 KB) ->
// grid 1024 with NO extra chip-wide staging traffic; smem ~22.5 KB -> 8 CTA/SM.
#define FT_ROWS 64
#define RG 4
#define KVT_ROW 36
__global__ void __launch_bounds__(256)
fuse_kernel(const __half* __restrict__ qkvo,
            const float* __restrict__ sinp, const float* __restrict__ cosp,
            const float* __restrict__ W_lepe, const float* __restrict__ b_lepe,
            __half* __restrict__ ph)
{
    __shared__ float skvT[4 * HD * KVT_ROW];    // 18432 B: kvT[hl][e][dd]
    __shared__ float sqs[8][RG][HD];            // 4096 B, per-warp slot

    const int tile = blockIdx.x;
    const int chh = tile & 1;                   // channel half
    const int tt  = tile >> 1;
    const int b   = tt / (NN / FT_ROWS);
    const int t   = tt % (NN / FT_ROWS);
    const int cb  = chh * 128;                  // channel base

    const int tid  = threadIdx.x;
    const int w    = tid >> 5;
    const int lane = tid & 31;
    const int hl   = w & 3;                     // head-local 0..3
    const int rh   = w >> 2;                    // row half 0..1
    const int c    = cb + hl * HD + lane;       // global channel
    const int h    = c >> 5;
    const int n0   = t * FT_ROWS + rh * 32;     // this warp's first row (local)
    const float inv_scale_n = SCALE_F / (float)NN;

    // stage 4 heads' kvT (transposed)
    const int base_kv = b * HH * HD * HD + cb * HD * 4 / 4;  // = b*8192 + (cb/32)*1024
#pragma unroll
    for (int ii = 0; ii < 16; ii++) {
        int i = ii * 256 + tid;                 // 0..4095
        int hh = i >> 10, dd = (i >> 5) & 31, e = i & 31;
        skvT[hh * (HD * KVT_ROW) + e * KVT_ROW + dd] =
            g_kv[b * HH * HD * HD + (chh * 4 + hh) * 1024 + dd * 32 + e] * inv_scale_n;
    }
    (void)base_kv;

    const float km = g_ksum[(b * HH + h) * HD + lane];
    const float vm = g_vsum[(b * HH + h) * HD + lane] * (1.f / NN);
    __syncthreads();

    const float w0 = W_lepe[c * 3 + 0];
    const float w1 = W_lepe[c * 3 + 1];
    const float w2 = W_lepe[c * 3 + 2];
    const float bl = b_lepe[c];

    const size_t rowbase = (size_t)(b * NN + n0) * QKVO_COLS;
    float vp = (n0 > 0) ? __half2float(qkvo[rowbase - QKVO_COLS + 512 + c]) : 0.f;
    float vc = __half2float(qkvo[rowbase + 512 + c]);

    const float* kvT = &skvT[hl * (HD * KVT_ROW) + lane * KVT_ROW];

#pragma unroll 1
    for (int g = 0; g < 32; g += RG) {
        const size_t r0 = rowbase + (size_t)g * QKVO_COLS;

        float vn[RG];
#pragma unroll
        for (int i = 0; i < RG - 1; i++)
            vn[i] = __half2float(qkvo[r0 + (size_t)(i + 1) * QKVO_COLS + 512 + c]);
        vn[RG - 1] = (n0 + g + RG < NN)
                   ? __half2float(qkvo[r0 + (size_t)RG * QKVO_COLS + 512 + c]) : 0.f;

        float qv[RG], ov[RG];
#pragma unroll
        for (int i = 0; i < RG; i++) {
            qv[i] = __half2float(qkvo[r0 + (size_t)i * QKVO_COLS + c]);
            ov[i] = __half2float(qkvo[r0 + (size_t)i * QKVO_COLS + 768 + c]);
        }

        float qh[RG];
#pragma unroll
        for (int i = 0; i < RG; i++)
            qh[i] = (qv[i] > 0.f) ? (qv[i] + 1.f) : __expf(qv[i]);

        float zp[RG];
#pragma unroll
        for (int i = 0; i < RG; i++) zp[i] = qh[i] * km;
#pragma unroll
        for (int off = 16; off > 0; off >>= 1) {
#pragma unroll
            for (int i = 0; i < RG; i++)
                zp[i] += __shfl_xor_sync(0xffffffffu, zp[i], off);
        }

#pragma unroll
        for (int i = 0; i < RG; i++) {
            float partner = __shfl_xor_sync(0xffffffffu, qh[i], 1);
            float sv = sinp[(n0 + g + i) * HD + lane];
            float cv = cosp[(n0 + g + i) * HD + lane];
            float rot = (lane & 1) ? partner : -partner;
            sqs[w][i][lane] = qh[i] * cv + rot * sv;
        }
        __syncwarp();

        float acc[RG];
#pragma unroll
        for (int i = 0; i < RG; i++) acc[i] = 0.f;
#pragma unroll
        for (int dq = 0; dq < 32; dq += 4) {
            float4 kvv = *(const float4*)&kvT[dq];
#pragma unroll
            for (int i = 0; i < RG; i++) {
                float4 qq = *(const float4*)&sqs[w][i][dq];
                acc[i] += qq.x * kvv.x + qq.y * kvv.y
                        + qq.z * kvv.z + qq.w * kvv.w;
            }
        }
        __syncwarp();

#pragma unroll
        for (int i = 0; i < RG; i++) {
            float z = zp[i] * inv_scale_n;
            float coef = 1.f + 1.f / (z + 1e-6f);
            float prev = (i == 0) ? vp : ((i == 1) ? vc : vn[i - 2]);
            float cur  = (i == 0) ? vc : vn[i - 1];
            float next = vn[i];
            float res  = acc[i] * coef - z * vm;
            float lepe = prev * w0 + cur * w1 + next * w2 + bl;
            ph[(size_t)(b * NN + n0 + g + i) * INTERNAL + c] =
                __float2half((res + lepe) * ov[i]);
        }

        vp = vn[RG - 2];
        vc = vn[RG - 1];
    }
}

// ---------------- launch -----------------------------------------------------
extern "C" void kernel_launch(void* const* d_in, const int* in_sizes, int n_in,
                              void* d_out, int out_size)
{
    const float* x       = (const float*)d_in[0];
    const float* sinp    = (const float*)d_in[1];
    const float* cosp    = (const float*)d_in[2];
    const float* W_qkvo  = (const float*)d_in[3];
    const float* b_qkvo  = (const float*)d_in[4];
    const float* W_lepe  = (const float*)d_in[5];
    const float* b_lepe  = (const float*)d_in[6];
    const float* W_proj  = (const float*)d_in[7];
    const float* b_proj  = (const float*)d_in[8];
    float* out = (float*)d_out;

    __half *qkvo_p, *xh, *ph, *wqh, *pwh;
    cudaGetSymbolAddress((void**)&qkvo_p, g_qkvo);
    cudaGetSymbolAddress((void**)&xh,  g_xh);
    cudaGetSymbolAddress((void**)&ph,  g_ph);
    cudaGetSymbolAddress((void**)&wqh, g_wqh);
    cudaGetSymbolAddress((void**)&pwh, g_pwh);

    cudaFuncSetAttribute(gemm_h_kernel<__half>,
                         cudaFuncAttributeMaxDynamicSharedMemorySize, GEMM_SMEM_BYTES);
    cudaFuncSetAttribute(gemm_h_kernel<float>,
                         cudaFuncAttributeMaxDynamicSharedMemorySize, GEMM_SMEM_BYTES);
    cudaFuncSetAttribute(stats_kernel,
                         cudaFuncAttributeMaxDynamicSharedMemorySize, STATS_SMEM);

    cvt_all_kernel<<<(CVT_N1 + CVT_N2 + CVT_N3 + 255) / 256, 256>>>(
        x, W_qkvo, W_proj, xh, wqh, pwh);

    // GEMM1: qkvo = x @ W_qkvo^T + b_qkvo   [32768 x 1024] -> fp16
    gemm_h_kernel<__half><<<dim3(QKVO_COLS / 128, MROWS / 128), 256, GEMM_SMEM_BYTES>>>(
        xh, wqh, b_qkvo, qkvo_p, MROWS, QKVO_COLS, DIMV);

    stats_kernel<<<dim3(BB * HH, 32), 256, STATS_SMEM>>>(qkvo_p, sinp, cosp);

    // fuse: 64-token x 4-head blocks, grid = B*(N/64)*2
    fuse_kernel<<<BB * (NN / FT_ROWS) * 2, 256>>>(qkvo_p, sinp, cosp,
                                                  W_lepe, b_lepe, ph);

    // GEMM2: out = pre @ W_proj^T + b_proj  [32768 x 256] -> fp32
    gemm_h_kernel<float><<<dim3(INTERNAL / 128, MROWS / 128), 256, GEMM_SMEM_BYTES>>>(
        ph, pwh, b_proj, out, MROWS, INTERNAL, DIMV);
}

// round 17
// speedup vs baseline: 1.0211x; 1.0211x over previous
#include <cuda_runtime.h>
#include <cuda_fp16.h>
#include <math.h>
#include <stdint.h>

#define BB 4
#define NN 8192
#define DIMV 256
#define HH 8
#define HD 32
#define INTERNAL 256
#define MROWS (BB * NN)        // 32768
#define QKVO_COLS 1024
#define SCALE_F 0.17677669529663687f

// ---------------- persistent device scratch (no allocations) ----------------
__device__ __half g_qkvo[(size_t)MROWS * QKVO_COLS];    // 67 MB fp16
__device__ __half g_xh [(size_t)MROWS * DIMV];
__device__ __half g_ph [(size_t)MROWS * INTERNAL];
__device__ __half g_wqh[(size_t)QKVO_COLS * DIMV];
__device__ __half g_pwh[(size_t)DIMV * INTERNAL];
__device__ float g_kv  [BB * HH * HD * HD];
__device__ float g_ksum[BB * HH * HD];
__device__ float g_vsum[BB * HH * HD];

__device__ __forceinline__ uint32_t smem_u32(const void* p) {
    uint32_t a;
    asm("{ .reg .u64 t; cvta.to.shared.u64 t, %1; cvt.u32.u64 %0, t; }"
        : "=r"(a) : "l"(p));
    return a;
}

__device__ __forceinline__ void ldmx4(uint32_t* r, uint32_t addr) {
    asm volatile("ldmatrix.sync.aligned.m8n8.x4.shared.b16 {%0,%1,%2,%3}, [%4];"
        : "=r"(r[0]), "=r"(r[1]), "=r"(r[2]), "=r"(r[3]) : "r"(addr));
}
__device__ __forceinline__ void ldmx2(uint32_t* r, uint32_t addr) {
    asm volatile("ldmatrix.sync.aligned.m8n8.x2.shared.b16 {%0,%1}, [%2];"
        : "=r"(r[0]), "=r"(r[1]) : "r"(addr));
}

__device__ __forceinline__ void mma16816h(float* d, const uint32_t* a,
                                          uint32_t b0, uint32_t b1) {
    asm volatile(
        "mma.sync.aligned.m16n8k16.row.col.f32.f16.f16.f32 "
        "{%0,%1,%2,%3}, {%4,%5,%6,%7}, {%8,%9}, {%0,%1,%2,%3};"
        : "+f"(d[0]), "+f"(d[1]), "+f"(d[2]), "+f"(d[3])
        : "r"(a[0]), "r"(a[1]), "r"(a[2]), "r"(a[3]), "r"(b0), "r"(b1));
}

__device__ __forceinline__ void cp16(uint32_t saddr, const void* gaddr) {
    asm volatile("cp.async.cg.shared.global [%0], [%1], 16;"
        :: "r"(saddr), "l"(gaddr) : "memory");
}
#define CP_COMMIT() asm volatile("cp.async.commit_group;" ::: "memory")
#define CP_WAIT(n)  asm volatile("cp.async.wait_group %0;" :: "n"(n) : "memory")

// ---------------- fused fp32->fp16 conversion + accumulator zeroing ---------
#define CVT_N1 (MROWS * DIMV / 4)
#define CVT_N2 (QKVO_COLS * DIMV / 4)
#define CVT_N3 (DIMV * INTERNAL / 4)
__global__ void __launch_bounds__(256)
cvt_all_kernel(const float* __restrict__ x, const float* __restrict__ wq,
               const float* __restrict__ pw, __half* __restrict__ xh,
               __half* __restrict__ wqh, __half* __restrict__ pwh)
{
    int i = blockIdx.x * 256 + threadIdx.x;
    if (i < BB * HH * HD * HD) g_kv[i] = 0.f;
    if (i < BB * HH * HD) { g_ksum[i] = 0.f; g_vsum[i] = 0.f; }

    const float* s; __half* d; int j;
    if (i < CVT_N1) { s = x; d = xh; j = i; }
    else if (i < CVT_N1 + CVT_N2) { s = wq; d = wqh; j = i - CVT_N1; }
    else if (i < CVT_N1 + CVT_N2 + CVT_N3) { s = pw; d = pwh; j = i - CVT_N1 - CVT_N2; }
    else return;
    float4 v = ((const float4*)s)[j];
    __half2 h0 = __floats2half2_rn(v.x, v.y);
    __half2 h1 = __floats2half2_rn(v.z, v.w);
    uint2 o = { *reinterpret_cast<uint32_t*>(&h0), *reinterpret_cast<uint32_t*>(&h1) };
    ((uint2*)d)[j] = o;
}

// =================== HMMA GEMM (single fp16, 4-stage cp.async) ==============
#define ROWB 80
#define ST_A 0
#define ST_B 10240
#define STAGEB 20480
#define NSTAGE 4
#define GEMM_SMEM_BYTES (NSTAGE * STAGEB)   // 80 KB

template <typename OutT>
__global__ void __launch_bounds__(256)
gemm_h_kernel(const __half* __restrict__ A, const __half* __restrict__ Bw,
              const float* __restrict__ bias, OutT* __restrict__ C,
              int M, int Nn, int K)
{
    extern __shared__ char sm[];
    const uint32_t smb = smem_u32(sm);
    const int tid  = threadIdx.x;
    const int wid  = tid >> 5;
    const int lane = tid & 31;
    const int m0 = blockIdx.y * 128;
    const int n0 = blockIdx.x * 128;
    const int wm0 = (wid & 3) * 32;
    const int wn0 = (wid >> 2) * 64;

    const int a_row = (lane & 7) + ((lane >> 3) & 1) * 8;
    const int a_kh  = (lane >> 4) * 8;
    const int b_row = (lane & 7) + ((lane >> 4) & 1) * 8;
    const int b_kh  = ((lane >> 3) & 1) * 8;

    float acc[2][8][4];
#pragma unroll
    for (int i = 0; i < 2; i++)
#pragma unroll
        for (int j = 0; j < 8; j++)
#pragma unroll
            for (int l = 0; l < 4; l++) acc[i][j][l] = 0.f;

    const int NCH = K / 32;
    const int row2 = tid >> 2;
    const int seg  = tid & 3;

#define LOAD_STAGE(c, buf) do {                                              \
    int k0 = (c) * 32;                                                       \
    uint32_t base = smb + (buf) * STAGEB;                                    \
    _Pragma("unroll")                                                        \
    for (int i = 0; i < 2; i++) {                                            \
        int r = row2 + i * 64;                                               \
        uint32_t so = r * ROWB + seg * 16;                                   \
        cp16(base + ST_A + so, A  + (size_t)(m0 + r) * K + k0 + seg * 8);    \
        cp16(base + ST_B + so, Bw + (size_t)(n0 + r) * K + k0 + seg * 8);    \
    }                                                                        \
    CP_COMMIT();                                                             \
} while (0)

    LOAD_STAGE(0, 0);
    LOAD_STAGE(1, 1);
    LOAD_STAGE(2, 2);

    for (int c = 0; c < NCH; c++) {
        CP_WAIT(2);
        __syncthreads();   // all warps past iter c-1's MMAs; stage c visible
        const uint32_t base = smb + (c & (NSTAGE - 1)) * STAGEB;

#pragma unroll
        for (int ks = 0; ks < 2; ks++) {
            uint32_t af[2][4], bf[4][4];
#pragma unroll
            for (int mf = 0; mf < 2; mf++)
                ldmx4(af[mf], base + ST_A + (wm0 + mf * 16 + a_row) * ROWB
                                        + (ks * 16 + a_kh) * 2);
#pragma unroll
            for (int nf2 = 0; nf2 < 4; nf2++)
                ldmx4(bf[nf2], base + ST_B + (wn0 + nf2 * 16 + b_row) * ROWB
                                          + (ks * 16 + b_kh) * 2);
#pragma unroll
            for (int nf2 = 0; nf2 < 4; nf2++)
#pragma unroll
                for (int mf = 0; mf < 2; mf++)
#pragma unroll
                    for (int s = 0; s < 2; s++)
                        mma16816h(acc[mf][nf2 * 2 + s], af[mf],
                                  bf[nf2][s * 2], bf[nf2][s * 2 + 1]);
        }
        // No second barrier: LOAD(c+3) writes buf (c-1)&3, which no warp can
        // still be reading (readers <=c-1 are barred by the top sync).
        if (c + 3 < NCH) LOAD_STAGE(c + 3, (c + 3) & (NSTAGE - 1));
        else CP_COMMIT();
    }
#undef LOAD_STAGE

    const int rr = lane >> 2;
    const int cc = (lane & 3) * 2;
#pragma unroll
    for (int mf = 0; mf < 2; mf++) {
        int r0 = m0 + wm0 + mf * 16 + rr;
#pragma unroll
        for (int nf = 0; nf < 8; nf++) {
            int col = n0 + wn0 + nf * 8 + cc;
            float b0 = bias[col], b1 = bias[col + 1];
            float o00 = acc[mf][nf][0] + b0, o01 = acc[mf][nf][1] + b1;
            float o10 = acc[mf][nf][2] + b0, o11 = acc[mf][nf][3] + b1;
            if (sizeof(OutT) == 2) {
                __half2 p0 = __floats2half2_rn(o00, o01);
                __half2 p1 = __floats2half2_rn(o10, o11);
                *(__half2*)&C[(size_t)r0 * Nn + col] = p0;
                *(__half2*)&C[(size_t)(r0 + 8) * Nn + col] = p1;
            } else {
                float2 v0 = {o00, o01}, v1 = {o10, o11};
                *(float2*)&C[(size_t)r0 * Nn + col] = v0;
                *(float2*)&C[(size_t)(r0 + 8) * Nn + col] = v1;
            }
        }
    }
}

// ---------------- stats v5: tensor-core kv_state, smem reuse ----------------
#define STW 5120
#define KVROW 34
#define STATS_SMEM (8 * STW)       // 40960 B

__global__ void __launch_bounds__(256)
stats_kernel(const __half* __restrict__ qkvo,
             const float* __restrict__ sinp, const float* __restrict__ cosp)
{
    extern __shared__ char ssm[];
    const int tid  = threadIdx.x;
    const int w    = tid >> 5;
    const int lane = tid & 31;
    const int bh = blockIdx.x;
    const int b = bh >> 3, h = bh & 7;
    const int nb = blockIdx.y * 256 + w * 32;

    char* smw = ssm + w * STW;
    char* smv = smw + 2560;
    const uint32_t ks_u = smem_u32(smw);
    const uint32_t v_u  = smem_u32(smv);

    const __half* kbase = qkvo + (size_t)(b * NN + nb) * QKVO_COLS + 256 + h * 32 + lane;
    const __half* vbase = kbase + 256;

    float ksum_acc = 0.f, vsum_acc = 0.f;

#pragma unroll
    for (int g = 0; g < 4; g++) {
        float kr[8], vr[8], sv[8], cv[8];
#pragma unroll
        for (int i = 0; i < 8; i++) {
            kr[i] = __half2float(kbase[(size_t)(g * 8 + i) * QKVO_COLS]);
            vr[i] = __half2float(vbase[(size_t)(g * 8 + i) * QKVO_COLS]);
        }
#pragma unroll
        for (int i = 0; i < 8; i++) {
            sv[i] = sinp[(nb + g * 8 + i) * HD + lane];
            cv[i] = cosp[(nb + g * 8 + i) * HD + lane];
        }
        __half ksh[8], vh[8];
#pragma unroll
        for (int i = 0; i < 8; i++) {
            float kh = (kr[i] > 0.f) ? (kr[i] + 1.f) : __expf(kr[i]);
            ksum_acc += kh;
            vsum_acc += vr[i];
            float partner = __shfl_xor_sync(0xffffffffu, kh, 1);
            float rot = (lane & 1) ? partner : -partner;
            ksh[i] = __float2half(kh * cv[i] + rot * sv[i]);
            vh[i]  = __float2half(vr[i]);
        }
#pragma unroll
        for (int i = 0; i < 8; i += 2) {
            int n = g * 8 + i;
            __half2 pk = {ksh[i], ksh[i + 1]};
            __half2 pv = {vh[i],  vh[i + 1]};
            *(__half2*)(smw + lane * 80 + n * 2) = pk;
            *(__half2*)(smv + lane * 80 + n * 2) = pv;
        }
    }
    __syncwarp();

    float kv[2][4][4];
#pragma unroll
    for (int mt = 0; mt < 2; mt++)
#pragma unroll
        for (int et = 0; et < 4; et++)
#pragma unroll
            for (int l = 0; l < 4; l++) kv[mt][et][l] = 0.f;

#pragma unroll
    for (int ks = 0; ks < 2; ks++) {
        const int k0 = ks * 16;
        uint32_t af[2][4];
#pragma unroll
        for (int mt = 0; mt < 2; mt++)
            ldmx4(af[mt], ks_u + (mt * 16 + (lane & 7) + ((lane >> 3) & 1) * 8) * 80
                               + (k0 + (lane >> 4) * 8) * 2);
#pragma unroll
        for (int et = 0; et < 4; et++) {
            uint32_t bf[2];
            ldmx2(bf, v_u + (et * 8 + (lane & 7)) * 80
                          + (k0 + ((lane >> 3) & 1) * 8) * 2);
#pragma unroll
            for (int mt = 0; mt < 2; mt++)
                mma16816h(kv[mt][et], af[mt], bf[0], bf[1]);
        }
    }
    __syncwarp();

    float* kvw = (float*)(ssm + w * STW);
    const int dm = lane >> 2;
    const int de = (lane & 3) * 2;
#pragma unroll
    for (int mt = 0; mt < 2; mt++)
#pragma unroll
        for (int et = 0; et < 4; et++) {
            float2 lo = {kv[mt][et][0], kv[mt][et][1]};
            float2 hi = {kv[mt][et][2], kv[mt][et][3]};
            *(float2*)&kvw[(mt * 16 + dm) * KVROW + et * 8 + de] = lo;
            *(float2*)&kvw[(mt * 16 + dm + 8) * KVROW + et * 8 + de] = hi;
        }

    atomicAdd(&g_ksum[bh * HD + lane], ksum_acc);
    atomicAdd(&g_vsum[bh * HD + lane], vsum_acc);

    __syncthreads();

    const float* kvs = (const float*)ssm;
#pragma unroll
    for (int o = 0; o < 4; o++) {
        int idx = o * 256 + tid;
        int m = idx >> 5, e = idx & 31;
        float s = 0.f;
#pragma unroll
        for (int ww = 0; ww < 8; ww++)
            s += kvs[ww * (STW / 4) + m * KVROW + e];
        atomicAdd(&g_kv[bh * (HD * HD) + m * HD + e], s);
    }
}

// ---------------- fused per-token epilogue (smem matvec, fp16 qkvo) ---------
// R15 config (measured best) + minBlocksPerMultiprocessor=5 to lift the
// register-occupancy cap (54 regs -> 4 CTAs was the binder; force <=51).
#define TILE_ROWS 64
#define RG 4
#define KVT_ROW 36
__global__ void __launch_bounds__(256, 5)
fuse_kernel(const __half* __restrict__ qkvo,
            const float* __restrict__ sinp, const float* __restrict__ cosp,
            const float* __restrict__ W_lepe, const float* __restrict__ b_lepe,
            __half* __restrict__ ph)
{
    __shared__ float skvT[HH * HD * KVT_ROW];   // 36864 B
    __shared__ float sqs[HH][RG][HD];           // 4096 B

    const int tile = blockIdx.x;
    const int b  = tile / (NN / TILE_ROWS);
    const int t  = tile % (NN / TILE_ROWS);
    const int n0 = t * TILE_ROWS;
    const int c  = threadIdx.x;
    const int h  = c >> 5;
    const int d  = c & 31;
    const float inv_scale_n = SCALE_F / (float)NN;

    const int base_kv = b * HH * HD * HD;
#pragma unroll
    for (int ii = 0; ii < HH * HD * HD / 256; ii++) {
        int i = ii * 256 + c;
        int hh = i >> 10, dd = (i >> 5) & 31, e = i & 31;
        skvT[hh * (HD * KVT_ROW) + e * KVT_ROW + dd] =
            g_kv[base_kv + i] * inv_scale_n;
    }

    const float km = g_ksum[(b * HH + h) * HD + d];
    const float vm = g_vsum[(b * HH + h) * HD + d] * (1.f / NN);
    __syncthreads();

    const float w0 = W_lepe[c * 3 + 0];
    const float w1 = W_lepe[c * 3 + 1];
    const float w2 = W_lepe[c * 3 + 2];
    const float bl = b_lepe[c];

    const size_t rowbase = (size_t)(b * NN + n0) * QKVO_COLS;
    float vp = (n0 > 0) ? __half2float(qkvo[rowbase - QKVO_COLS + 512 + c]) : 0.f;
    float vc = __half2float(qkvo[rowbase + 512 + c]);

    const float* kvT = &skvT[h * (HD * KVT_ROW) + d * KVT_ROW];

#pragma unroll 1
    for (int g = 0; g < TILE_ROWS; g += RG) {
        const size_t r0 = rowbase + (size_t)g * QKVO_COLS;

        float vn[RG];
#pragma unroll
        for (int i = 0; i < RG - 1; i++)
            vn[i] = __half2float(qkvo[r0 + (size_t)(i + 1) * QKVO_COLS + 512 + c]);
        vn[RG - 1] = (n0 + g + RG < NN)
                   ? __half2float(qkvo[r0 + (size_t)RG * QKVO_COLS + 512 + c]) : 0.f;

        float qv[RG], ov[RG];
#pragma unroll
        for (int i = 0; i < RG; i++) {
            qv[i] = __half2float(qkvo[r0 + (size_t)i * QKVO_COLS + c]);
            ov[i] = __half2float(qkvo[r0 + (size_t)i * QKVO_COLS + 768 + c]);
        }

        float qh[RG];
#pragma unroll
        for (int i = 0; i < RG; i++)
            qh[i] = (qv[i] > 0.f) ? (qv[i] + 1.f) : __expf(qv[i]);

        float zp[RG];
#pragma unroll
        for (int i = 0; i < RG; i++) zp[i] = qh[i] * km;
#pragma unroll
        for (int off = 16; off > 0; off >>= 1) {
#pragma unroll
            for (int i = 0; i < RG; i++)
                zp[i] += __shfl_xor_sync(0xffffffffu, zp[i], off);
        }

#pragma unroll
        for (int i = 0; i < RG; i++) {
            float partner = __shfl_xor_sync(0xffffffffu, qh[i], 1);
            float sv = sinp[(n0 + g + i) * HD + d];
            float cv = cosp[(n0 + g + i) * HD + d];
            float rot = (d & 1) ? partner : -partner;
            sqs[h][i][d] = qh[i] * cv + rot * sv;
        }
        __syncwarp();

        float acc[RG];
#pragma unroll
        for (int i = 0; i < RG; i++) acc[i] = 0.f;
#pragma unroll
        for (int dq = 0; dq < 32; dq += 4) {
            float4 kvv = *(const float4*)&kvT[dq];
#pragma unroll
            for (int i = 0; i < RG; i++) {
                float4 qq = *(const float4*)&sqs[h][i][dq];
                acc[i] += qq.x * kvv.x + qq.y * kvv.y
                        + qq.z * kvv.z + qq.w * kvv.w;
            }
        }
        __syncwarp();

#pragma unroll
        for (int i = 0; i < RG; i++) {
            float z = zp[i] * inv_scale_n;
            float coef = 1.f + 1.f / (z + 1e-6f);
            float prev = (i == 0) ? vp : ((i == 1) ? vc : vn[i - 2]);
            float cur  = (i == 0) ? vc : vn[i - 1];
            float next = vn[i];
            float res  = acc[i] * coef - z * vm;
            float lepe = prev * w0 + cur * w1 + next * w2 + bl;
            ph[(size_t)(b * NN + n0 + g + i) * INTERNAL + c] =
                __float2half((res + lepe) * ov[i]);
        }

        vp = vn[RG - 2];
        vc = vn[RG - 1];
    }
}

// ---------------- launch -----------------------------------------------------
extern "C" void kernel_launch(void* const* d_in, const int* in_sizes, int n_in,
                              void* d_out, int out_size)
{
    const float* x       = (const float*)d_in[0];
    const float* sinp    = (const float*)d_in[1];
    const float* cosp    = (const float*)d_in[2];
    const float* W_qkvo  = (const float*)d_in[3];
    const float* b_qkvo  = (const float*)d_in[4];
    const float* W_lepe  = (const float*)d_in[5];
    const float* b_lepe  = (const float*)d_in[6];
    const float* W_proj  = (const float*)d_in[7];
    const float* b_proj  = (const float*)d_in[8];
    float* out = (float*)d_out;

    __half *qkvo_p, *xh, *ph, *wqh, *pwh;
    cudaGetSymbolAddress((void**)&qkvo_p, g_qkvo);
    cudaGetSymbolAddress((void**)&xh,  g_xh);
    cudaGetSymbolAddress((void**)&ph,  g_ph);
    cudaGetSymbolAddress((void**)&wqh, g_wqh);
    cudaGetSymbolAddress((void**)&pwh, g_pwh);

    cudaFuncSetAttribute(gemm_h_kernel<__half>,
                         cudaFuncAttributeMaxDynamicSharedMemorySize, GEMM_SMEM_BYTES);
    cudaFuncSetAttribute(gemm_h_kernel<float>,
                         cudaFuncAttributeMaxDynamicSharedMemorySize, GEMM_SMEM_BYTES);
    cudaFuncSetAttribute(stats_kernel,
                         cudaFuncAttributeMaxDynamicSharedMemorySize, STATS_SMEM);

    cvt_all_kernel<<<(CVT_N1 + CVT_N2 + CVT_N3 + 255) / 256, 256>>>(
        x, W_qkvo, W_proj, xh, wqh, pwh);

    // GEMM1: qkvo = x @ W_qkvo^T + b_qkvo   [32768 x 1024] -> fp16
    gemm_h_kernel<__half><<<dim3(QKVO_COLS / 128, MROWS / 128), 256, GEMM_SMEM_BYTES>>>(
        xh, wqh, b_qkvo, qkvo_p, MROWS, QKVO_COLS, DIMV);

    stats_kernel<<<dim3(BB * HH, 32), 256, STATS_SMEM>>>(qkvo_p, sinp, cosp);

    fuse_kernel<<<BB * (NN / TILE_ROWS), 256>>>(qkvo_p, sinp, cosp,
                                                W_lepe, b_lepe, ph);

    // GEMM2: out = pre @ W_proj^T + b_proj  [32768 x 256] -> fp32
    gemm_h_kernel<float><<<dim3(INTERNAL / 128, MROWS / 128), 256, GEMM_SMEM_BYTES>>>(
        ph, pwh, b_proj, out, MROWS, INTERNAL, DIMV);
}